// round 5
// baseline (speedup 1.0000x reference)
#include <cuda_runtime.h>
#include <cuda_bf16.h>
#include <cstdint>

// Problem shape (fixed by the dataset)
#define BB 64
#define CC 256
#define HH 80
#define WW 80
#define NN 100
#define IMG 640.0f

#define NPLANES (BB * CC)          // 16384 planes
#define PLANE_ELEMS (HH * WW)      // 6400 floats
#define PSTRIDE 84                 // padded smem row stride (floats)
#define PBUF (HH * PSTRIDE)        // 6720 floats per group buffer (26.88 KB)
#define NG 6                       // groups per CTA
#define GW 4                       // warps per group
#define GRID 152                   // persistent, one CTA per SM
#define TPB (NG * GW * 32)         // 768 threads

__device__ __forceinline__ void named_bar(int id, int count) {
    asm volatile("bar.sync %0, %1;" :: "r"(id), "r"(count) : "memory");
}

__global__ __launch_bounds__(TPB, 1)
void roi_pool_kernel(const float* __restrict__ fmap,
                     const float* __restrict__ boxes,
                     float* __restrict__ out)
{
    extern __shared__ __align__(16) float P[];   // [NG][PBUF] = 161.3 KB

    const int tid  = threadIdx.x;
    const int wid  = tid >> 5;
    const int lane = tid & 31;
    const int bid  = blockIdx.x;

    const int g  = wid / GW;               // group 0..5
    const int wg = wid % GW;               // warp within group 0..3
    const int gt = (wid % GW) * 32 + lane; // 0..127 within group
    float* S = P + g * PBUF;

    const int G = bid * NG + g;            // global group id 0..911
    const int cg = (lane < 20) ? lane : 19;  // column-group for float4 load
    const bool ld_active = (lane < 20);

    for (int it = 0; ; ++it) {
        const int p = G + it * (GRID * NG);
        if (p >= NPLANES) break;
        const float* plane = fmap + (size_t)p * PLANE_ELEMS;

        // ============ Pass A: row prefix scan (axis x) from GMEM ============
        // Warp wg owns rows wg, wg+4, ..., wg+76 (20 rows). For each row,
        // lanes 0..19 hold float4 raw[row][4*lane .. 4*lane+3] (coalesced
        // 320B LDG.128). Depth-4 pipeline keeps 4 rows of loads in flight.
        {
            float4 buf[4];
            #pragma unroll
            for (int d = 0; d < 4; ++d) {
                const int r = wg + 4 * d;
                buf[d] = __ldg(reinterpret_cast<const float4*>(plane + r * WW) + cg);
            }
            #pragma unroll
            for (int k = 0; k < 20; ++k) {
                float4 v = buf[k & 3];
                const int r = wg + 4 * k;
                const int kn = k + 4;
                if (kn < 20)
                    buf[k & 3] = __ldg(reinterpret_cast<const float4*>(
                                           plane + (wg + 4 * kn) * WW) + cg);

                // local inclusive prefix of the 4 elements
                v.y += v.x; v.z += v.y; v.w += v.z;
                // inclusive scan of lane totals over lanes 0..19
                float tot = v.w;
                #pragma unroll
                for (int d = 1; d < 32; d <<= 1) {
                    float o = __shfl_up_sync(0xFFFFFFFFu, tot, d);
                    if (lane >= d) tot += o;
                }
                const float excl = tot - v.w;   // exclusive offset for this lane
                v.x += excl; v.y += excl; v.z += excl; v.w += excl;

                if (ld_active)
                    *reinterpret_cast<float4*>(S + r * PSTRIDE + 4 * lane) = v;
            }
        }
        named_bar(g + 1, 128);

        // ============ Pass B: column prefix scan (axis y), in place ==========
        // Thread gt owns column gt; consecutive lanes -> consecutive banks.
        if (gt < WW) {
            float acc = 0.0f;
            #pragma unroll 16
            for (int y = 0; y < HH; ++y) {
                acc += S[y * PSTRIDE + gt];
                S[y * PSTRIDE + gt] = acc;
            }
        }
        named_bar(g + 1, 128);

        // ============ Pass C: 100 boxes of batch p/CC ============
        if (gt < NN) {
            const int b = p / CC;
            const int c = p % CC;
            float4 bx = reinterpret_cast<const float4*>(boxes)[b * NN + gt];

            // Reference math exactly: (coord/640)*80 in fp32 RN, int
            // truncation (non-negative => floor), clip into [0, dim].
            int x1 = (int)__fmul_rn(__fdiv_rn(bx.x, IMG), (float)WW);
            int y1 = (int)__fmul_rn(__fdiv_rn(bx.y, IMG), (float)HH);
            int x2 = (int)__fmul_rn(__fdiv_rn(bx.z, IMG), (float)WW);
            int y2 = (int)__fmul_rn(__fdiv_rn(bx.w, IMG), (float)HH);
            x1 = min(max(x1, 0), WW);
            y1 = min(max(y1, 0), HH);
            x2 = min(max(x2, 0), WW);
            y2 = min(max(y2, 0), HH);

            const int dy = y2 - y1;
            const int dx = x2 - x1;
            float r = 0.0f;
            if (dy > 0 && dx > 0) {
                // Inclusive integral -> exclusive corners at (y-1,x-1); border 0.
                float s22 = S[(y2 - 1) * PSTRIDE + (x2 - 1)];
                float s12 = (y1 > 0) ? S[(y1 - 1) * PSTRIDE + (x2 - 1)] : 0.0f;
                float s21 = (x1 > 0) ? S[(y2 - 1) * PSTRIDE + (x1 - 1)] : 0.0f;
                float s11 = (y1 > 0 && x1 > 0) ? S[(y1 - 1) * PSTRIDE + (x1 - 1)] : 0.0f;
                r = __fdiv_rn(s22 - s12 - s21 + s11, (float)(dy * dx));
            }
            out[((size_t)b * NN + gt) * CC + c] = r;
        }
        // All reads of S done before next iteration's row scan overwrites it.
        named_bar(g + 1, 128);
    }
}

extern "C" void kernel_launch(void* const* d_in, const int* in_sizes, int n_in,
                              void* d_out, int out_size)
{
    const float* fmap  = (const float*)d_in[0];   // [64,256,80,80]
    const float* boxes = (const float*)d_in[1];   // [64,100,4]
    float* out = (float*)d_out;                   // [64,100,256]

    const int smem_bytes = NG * PBUF * sizeof(float);   // 161280
    cudaFuncSetAttribute(roi_pool_kernel,
                         cudaFuncAttributeMaxDynamicSharedMemorySize,
                         smem_bytes);

    roi_pool_kernel<<<GRID, TPB, smem_bytes>>>(fmap, boxes, out);
}

// round 6
// speedup vs baseline: 1.2423x; 1.2423x over previous
#include <cuda_runtime.h>
#include <cuda_bf16.h>
#include <cstdint>

// Problem shape (fixed by the dataset)
#define BB 64
#define CC 256
#define HH 80
#define WW 80
#define NN 100
#define IMG 640.0f

#define NPLANES (BB * CC)          // 16384 planes
#define PLANE_ELEMS (HH * WW)      // 6400 floats
#define PSTRIDE 84                 // padded smem row stride (floats)
#define PBUF (HH * PSTRIDE)        // 6720 floats per group buffer (26.88 KB)
#define NG 6                       // independent groups per CTA
#define GW 4                       // warps per group (128 threads)
#define GRID 152                   // persistent, one CTA per SM
#define TPB (NG * GW * 32)         // 768 threads
#define PF 12                      // pass-1 prefetch depth (regs)

__device__ __forceinline__ void named_bar(int id, int count) {
    asm volatile("bar.sync %0, %1;" :: "r"(id), "r"(count) : "memory");
}

__global__ __launch_bounds__(TPB, 1)
void roi_pool_kernel(const float* __restrict__ fmap,
                     const float* __restrict__ boxes,
                     float* __restrict__ out)
{
    extern __shared__ __align__(16) float P[];   // [NG][PBUF] = 161.3 KB

    const int tid  = threadIdx.x;
    const int wid  = tid >> 5;
    const int lane = tid & 31;
    const int bid  = blockIdx.x;

    const int g  = wid / GW;                 // group 0..5
    const int gt = (wid % GW) * 32 + lane;   // 0..127 within group
    float* S = P + g * PBUF;

    const int G = bid * NG + g;              // global group id 0..911

    for (int it = 0; ; ++it) {
        const int p = G + it * (GRID * NG);
        if (p >= NPLANES) break;
        const float* plane = fmap + (size_t)p * PLANE_ELEMS;

        // ===== Pass 1: column cumsum (axis y) fused with the GMEM load. =====
        // Lane gt<80 owns column gt. Coalesced: fixed y, lanes read 320B.
        // PF-deep rotating prefetch keeps ~PF rows of loads in flight per
        // column; accumulation is a 4-cyc FADD chain (NO shuffles).
        if (gt < WW) {
            float buf[PF];
            #pragma unroll
            for (int d = 0; d < PF; ++d)
                buf[d] = __ldg(plane + d * WW + gt);

            float acc = 0.0f;
            #pragma unroll
            for (int y = 0; y < HH; ++y) {
                float v = buf[y % PF];
                const int yn = y + PF;
                if (yn < HH)
                    buf[y % PF] = __ldg(plane + yn * WW + gt);
                acc += v;
                S[y * PSTRIDE + gt] = acc;   // conflict-free (consecutive banks)
            }
        }
        named_bar(g + 1, 128);

        // ===== Pass 2: row cumsum (axis x), per row, float4, in place. =====
        // Row stride 21 float4: within each 8-lane phase, (21*t+g) mod 8
        // distinct -> conflict-free. S becomes the INCLUSIVE integral image.
        if (gt < HH) {
            float4* row = reinterpret_cast<float4*>(S + gt * PSTRIDE);
            float acc = 0.0f;
            #pragma unroll
            for (int q = 0; q < WW / 4; ++q) {
                float4 v4 = row[q];
                v4.x += acc;
                v4.y += v4.x;
                v4.z += v4.y;
                v4.w += v4.z;
                acc = v4.w;
                row[q] = v4;
            }
        }
        named_bar(g + 1, 128);

        // ===== Pass 3: evaluate the 100 boxes of batch p/CC. =====
        if (gt < NN) {
            const int b = p / CC;
            const int c = p % CC;
            float4 bx = reinterpret_cast<const float4*>(boxes)[b * NN + gt];

            // Reference math exactly: (coord/640)*80 in fp32 RN, int
            // truncation (non-negative => floor), clip into [0, dim].
            int x1 = (int)__fmul_rn(__fdiv_rn(bx.x, IMG), (float)WW);
            int y1 = (int)__fmul_rn(__fdiv_rn(bx.y, IMG), (float)HH);
            int x2 = (int)__fmul_rn(__fdiv_rn(bx.z, IMG), (float)WW);
            int y2 = (int)__fmul_rn(__fdiv_rn(bx.w, IMG), (float)HH);
            x1 = min(max(x1, 0), WW);
            y1 = min(max(y1, 0), HH);
            x2 = min(max(x2, 0), WW);
            y2 = min(max(y2, 0), HH);

            const int dy = y2 - y1;
            const int dx = x2 - x1;
            float r = 0.0f;
            if (dy > 0 && dx > 0) {
                // Inclusive integral -> exclusive corners at (y-1,x-1); border 0.
                float s22 = S[(y2 - 1) * PSTRIDE + (x2 - 1)];
                float s12 = (y1 > 0) ? S[(y1 - 1) * PSTRIDE + (x2 - 1)] : 0.0f;
                float s21 = (x1 > 0) ? S[(y2 - 1) * PSTRIDE + (x1 - 1)] : 0.0f;
                float s11 = (y1 > 0 && x1 > 0) ? S[(y1 - 1) * PSTRIDE + (x1 - 1)] : 0.0f;
                r = __fdiv_rn(s22 - s12 - s21 + s11, (float)(dy * dx));
            }
            out[((size_t)b * NN + gt) * CC + c] = r;
        }
        // All reads of S done before next iteration's pass 1 overwrites it.
        named_bar(g + 1, 128);
    }
}

extern "C" void kernel_launch(void* const* d_in, const int* in_sizes, int n_in,
                              void* d_out, int out_size)
{
    const float* fmap  = (const float*)d_in[0];   // [64,256,80,80]
    const float* boxes = (const float*)d_in[1];   // [64,100,4]
    float* out = (float*)d_out;                   // [64,100,256]

    const int smem_bytes = NG * PBUF * sizeof(float);   // 161280
    cudaFuncSetAttribute(roi_pool_kernel,
                         cudaFuncAttributeMaxDynamicSharedMemorySize,
                         smem_bytes);

    roi_pool_kernel<<<GRID, TPB, smem_bytes>>>(fmap, boxes, out);
}